// round 3
// baseline (speedup 1.0000x reference)
#include <cuda_runtime.h>

#define NN 50000
#define EE 1600000
#define D  64

// ---- scratch (static device memory). float4/float2 types => alignment. ----
__device__ float4 g_hmu4[NN * 16];   // relu(mu @ W3.T)
__device__ float4 g_hmw4[NN * 16];   // g_hmu @ W4c.T
__device__ int    g_deg [NN];        // out-degree histogram (by src)
__device__ int    g_off [NN + 1];    // exclusive prefix (CSR row offsets)
__device__ int    g_cur [NN];        // scatter cursors (consumed copy)
__device__ int    g_pdst[EE];        // dst permuted into src-sorted order
__device__ float  g_pew [EE];        // edge_w permuted into src-sorted order
__device__ float2 g_a1[32], g_a2[32], g_b1[32], g_b2[32];

// ---- zero the histogram (graph-replay safe) ----
__global__ void zero_kernel() {
    int i = blockIdx.x * blockDim.x + threadIdx.x;
    if (i < NN) g_deg[i] = 0;
}

// ---- histogram of src ----
__global__ __launch_bounds__(256) void hist_kernel(const int* __restrict__ ei) {
    int e = blockIdx.x * 256 + threadIdx.x;   // grid covers EE exactly
    atomicAdd(&g_deg[ei[e]], 1);
}

// ---- single-block exclusive scan over 50000 bins ----
__global__ __launch_bounds__(1024) void scan_kernel() {
    __shared__ int sums[1024];
    const int PER = 49;                       // 1024*49 = 50176 >= NN
    int t = threadIdx.x;
    int base = t * PER;
    int s = 0;
    #pragma unroll 7
    for (int i = 0; i < PER; i++) {
        int b = base + i;
        s += (b < NN) ? g_deg[b] : 0;
    }
    sums[t] = s;
    __syncthreads();
    for (int d = 1; d < 1024; d <<= 1) {
        int u = (t >= d) ? sums[t - d] : 0;
        __syncthreads();
        sums[t] += u;
        __syncthreads();
    }
    int off = sums[t] - s;                    // exclusive prefix for this thread
    #pragma unroll 7
    for (int i = 0; i < PER; i++) {
        int b = base + i;
        if (b < NN) {
            int dg = g_deg[b];
            g_off[b] = off;
            g_cur[b] = off;
            off += dg;
        }
    }
    if (t == 1023) g_off[NN] = off;           // == EE
}

// ---- scatter edges into src-sorted order ----
__global__ __launch_bounds__(256) void scatter_kernel(const int* __restrict__ ei,
                                                      const float* __restrict__ ew) {
    int e = blockIdx.x * 256 + threadIdx.x;   // grid covers EE exactly
    int src = ei[e];
    int pos = atomicAdd(&g_cur[src], 1);
    g_pdst[pos] = ei[EE + e];
    g_pew[pos]  = ew[e];
}

// ---- precompute the 4 collapsed vectors ----
__global__ void vec_kernel(const float* __restrict__ W1, const float* __restrict__ W2,
                           const float* __restrict__ W4) {
    int o2 = threadIdx.x;   // 0..63
    float a1 = 0.f, a2 = 0.f, b1 = 0.f, b2 = 0.f;
    for (int o = 0; o < D; o++) {
        float w4a = W4[o2 * 192 + o];
        float w4b = W4[o2 * 192 + 64 + o];
        float w1 = W1[o], w2 = W2[o];
        a1 = fmaf(w4a, fmaxf(w1, 0.f), a1);
        a2 = fmaf(w4a, fmaxf(-w1, 0.f), a2);
        b1 = fmaf(w4b, fmaxf(w2, 0.f), b1);
        b2 = fmaf(w4b, fmaxf(-w2, 0.f), b2);
    }
    reinterpret_cast<float*>(g_a1)[o2] = a1;
    reinterpret_cast<float*>(g_a2)[o2] = a2;
    reinterpret_cast<float*>(g_b1)[o2] = b1;
    reinterpret_cast<float*>(g_b2)[o2] = b2;
}

// ---- fused dual GEMM: h_mu = relu(mu@W3.T); hmw = h_mu @ W4c.T ----
__global__ __launch_bounds__(256) void gemm_kernel(const float* __restrict__ mu,
                                                   const float* __restrict__ W3,
                                                   const float* __restrict__ W4) {
    __shared__ float W3T[D * D];
    __shared__ float W4cT[D * D];
    __shared__ float mus[16 * 68];
    __shared__ float hs [16 * 68];

    int t = threadIdx.x;
    for (int i = t; i < D * D; i += 256) {
        int o = i >> 6, k = i & 63;
        W3T [k * D + o] = W3[i];
        W4cT[k * D + o] = W4[o * 192 + 128 + k];
    }

    int g = t >> 4;
    int q = t & 15;
    const float4* W3T4  = reinterpret_cast<const float4*>(W3T);
    const float4* W4cT4 = reinterpret_cast<const float4*>(W4cT);

    int n = blockIdx.x * 16 + g;              // grid = 3125 -> n < 50000 exactly
    float4 mrow = reinterpret_cast<const float4*>(mu)[n * 16 + q];
    __syncthreads();
    *reinterpret_cast<float4*>(&mus[g * 68 + 4 * q]) = mrow;
    __syncthreads();

    float4 acc = make_float4(0.f, 0.f, 0.f, 0.f);
    #pragma unroll
    for (int k = 0; k < D; k++) {
        float m = mus[g * 68 + k];
        float4 w = W3T4[k * 16 + q];
        acc.x = fmaf(m, w.x, acc.x); acc.y = fmaf(m, w.y, acc.y);
        acc.z = fmaf(m, w.z, acc.z); acc.w = fmaf(m, w.w, acc.w);
    }
    float4 h = make_float4(fmaxf(acc.x, 0.f), fmaxf(acc.y, 0.f),
                           fmaxf(acc.z, 0.f), fmaxf(acc.w, 0.f));
    *reinterpret_cast<float4*>(&hs[g * 68 + 4 * q]) = h;
    __syncthreads();

    float4 acc2 = make_float4(0.f, 0.f, 0.f, 0.f);
    #pragma unroll
    for (int j = 0; j < D; j++) {
        float hv = hs[g * 68 + j];
        float4 w = W4cT4[j * 16 + q];
        acc2.x = fmaf(hv, w.x, acc2.x); acc2.y = fmaf(hv, w.y, acc2.y);
        acc2.z = fmaf(hv, w.z, acc2.z); acc2.w = fmaf(hv, w.w, acc2.w);
    }
    g_hmu4[n * 16 + q] = h;
    g_hmw4[n * 16 + q] = acc2;
}

// ---- node kernel: atomic-free segment reduction + full epilogue ----
// One warp per node. Lane owns float2 (cols 2*lane, 2*lane+1).
__global__ __launch_bounds__(256) void node_kernel(const float* __restrict__ x,
                                                   const float* __restrict__ W1,
                                                   float* __restrict__ out) {
    int warp = blockIdx.x * 8 + (threadIdx.x >> 5);   // grid: 6250 blocks = 50000 warps
    int lane = threadIdx.x & 31;
    int n = warp;
    int beg = g_off[n], end = g_off[n + 1];

    const float2* hmw2 = reinterpret_cast<const float2*>(g_hmw4);
    float2 acc = make_float2(0.f, 0.f);
    float sp = 0.f, sm = 0.f, ewp = 0.f, ewm = 0.f;

    int e = beg;
    for (; e + 4 <= end; e += 4) {
        int d0 = g_pdst[e], d1 = g_pdst[e + 1], d2 = g_pdst[e + 2], d3 = g_pdst[e + 3];
        float2 v0 = hmw2[d0 * 32 + lane];
        float2 v1 = hmw2[d1 * 32 + lane];
        float2 v2 = hmw2[d2 * 32 + lane];
        float2 v3 = hmw2[d3 * 32 + lane];
        float w0 = g_pew[e], w1 = g_pew[e + 1], w2 = g_pew[e + 2], w3 = g_pew[e + 3];
        float x0 = __ldg(&x[d0]), x1 = __ldg(&x[d1]), x2 = __ldg(&x[d2]), x3 = __ldg(&x[d3]);
        acc.x += (v0.x + v1.x) + (v2.x + v3.x);
        acc.y += (v0.y + v1.y) + (v2.y + v3.y);
        sp  += (fmaxf(x0, 0.f) + fmaxf(x1, 0.f)) + (fmaxf(x2, 0.f) + fmaxf(x3, 0.f));
        sm  += (fmaxf(-x0, 0.f) + fmaxf(-x1, 0.f)) + (fmaxf(-x2, 0.f) + fmaxf(-x3, 0.f));
        ewp += (fmaxf(w0, 0.f) + fmaxf(w1, 0.f)) + (fmaxf(w2, 0.f) + fmaxf(w3, 0.f));
        ewm += (fmaxf(-w0, 0.f) + fmaxf(-w1, 0.f)) + (fmaxf(-w2, 0.f) + fmaxf(-w3, 0.f));
    }
    for (; e < end; e++) {
        int d0 = g_pdst[e];
        float2 v0 = hmw2[d0 * 32 + lane];
        float w0 = g_pew[e];
        float x0 = __ldg(&x[d0]);
        acc.x += v0.x; acc.y += v0.y;
        sp += fmaxf(x0, 0.f);  sm += fmaxf(-x0, 0.f);
        ewp += fmaxf(w0, 0.f); ewm += fmaxf(-w0, 0.f);
    }

    // epilogue: z = sp*a1 + sm*a2 + ewp*b1 + ewm*b2 + acc; out = relu(hx+hmu+relu(z))
    float2 A1 = g_a1[lane], A2 = g_a2[lane], B1 = g_b1[lane], B2 = g_b2[lane];
    float2 z;
    z.x = fmaf(sp, A1.x, fmaf(sm, A2.x, fmaf(ewp, B1.x, fmaf(ewm, B2.x, acc.x))));
    z.y = fmaf(sp, A1.y, fmaf(sm, A2.y, fmaf(ewp, B1.y, fmaf(ewm, B2.y, acc.y))));

    float xn = x[n];
    float2 w1 = reinterpret_cast<const float2*>(W1)[lane];
    float2 hmu = reinterpret_cast<const float2*>(g_hmu4)[n * 32 + lane];
    float2 o;
    o.x = fmaxf(fmaxf(xn * w1.x, 0.f) + hmu.x + fmaxf(z.x, 0.f), 0.f);
    o.y = fmaxf(fmaxf(xn * w1.y, 0.f) + hmu.y + fmaxf(z.y, 0.f), 0.f);
    reinterpret_cast<float2*>(out)[n * 32 + lane] = o;
}

extern "C" void kernel_launch(void* const* d_in, const int* in_sizes, int n_in,
                              void* d_out, int out_size) {
    const float* mu = (const float*)d_in[0];
    const float* x  = (const float*)d_in[1];
    const int*   ei = (const int*)d_in[2];
    const float* ew = (const float*)d_in[3];
    const float* W1 = (const float*)d_in[4];
    const float* W2 = (const float*)d_in[5];
    const float* W3 = (const float*)d_in[6];
    const float* W4 = (const float*)d_in[7];
    float* out = (float*)d_out;

    zero_kernel<<<(NN + 255) / 256, 256>>>();
    hist_kernel<<<EE / 256, 256>>>(ei);
    scan_kernel<<<1, 1024>>>();
    scatter_kernel<<<EE / 256, 256>>>(ei, ew);
    vec_kernel<<<1, 64>>>(W1, W2, W4);
    gemm_kernel<<<3125, 256>>>(mu, W3, W4);
    node_kernel<<<6250, 256>>>(x, W1, out);
}

// round 4
// speedup vs baseline: 1.5281x; 1.5281x over previous
#include <cuda_runtime.h>

#define NN 50000
#define EE 1600000
#define D  64

// ---- scratch (static device memory; zero-initialized at module load).
//      Accumulators are zero at every kernel_launch entry: final_kernel
//      restores zeros after consuming them, so graph replays are deterministic. ----
__device__ float4 g_hmu4[NN * 16];   // relu(mu @ W3.T)           (overwritten each call)
__device__ float4 g_hmw4[NN * 16];   // g_hmu @ W4c.T             (overwritten each call)
__device__ float4 g_S4  [NN * 16];   // segment-sum accumulator   (zero at entry)
__device__ float4 g_scal[NN];        // {sum relu(x), relu(-x), relu(w), relu(-w)} per src (zero at entry)
__device__ float  g_a1[D], g_a2[D], g_b1[D], g_b2[D];

// ---- precompute the 4 collapsed vectors ----
// a1 = W4[:,0:64]@relu(W1); a2 = W4[:,0:64]@relu(-W1)
// b1 = W4[:,64:128]@relu(W2); b2 = W4[:,64:128]@relu(-W2)
__global__ void vec_kernel(const float* __restrict__ W1, const float* __restrict__ W2,
                           const float* __restrict__ W4) {
    int o2 = threadIdx.x;   // 0..63
    float a1 = 0.f, a2 = 0.f, b1 = 0.f, b2 = 0.f;
    for (int o = 0; o < D; o++) {
        float w4a = W4[o2 * 192 + o];
        float w4b = W4[o2 * 192 + 64 + o];
        float w1 = W1[o], w2 = W2[o];
        a1 = fmaf(w4a, fmaxf(w1, 0.f), a1);
        a2 = fmaf(w4a, fmaxf(-w1, 0.f), a2);
        b1 = fmaf(w4b, fmaxf(w2, 0.f), b1);
        b2 = fmaf(w4b, fmaxf(-w2, 0.f), b2);
    }
    g_a1[o2] = a1; g_a2[o2] = a2; g_b1[o2] = b1; g_b2[o2] = b2;
}

// ---- fused dual GEMM: h_mu = relu(mu@W3.T); hmw = h_mu @ W4c.T ----
// persistent: 888 blocks, 16 nodes/block/iter, 16 threads per node (float4 outputs).
__global__ __launch_bounds__(256) void gemm_kernel(const float* __restrict__ mu,
                                                   const float* __restrict__ W3,
                                                   const float* __restrict__ W4) {
    __shared__ float W3T[D * D];    // W3T[k*64+o] = W3[o*64+k]
    __shared__ float W4cT[D * D];   // W4cT[j*64+o] = W4[o*192+128+j]
    __shared__ float mus[16 * 68];
    __shared__ float hs [16 * 68];

    int t = threadIdx.x;
    for (int i = t; i < D * D; i += 256) {
        int o = i >> 6, k = i & 63;
        W3T [k * D + o] = W3[i];
        W4cT[k * D + o] = W4[o * 192 + 128 + k];
    }

    int g = t >> 4;
    int q = t & 15;
    const float4* W3T4  = reinterpret_cast<const float4*>(W3T);
    const float4* W4cT4 = reinterpret_cast<const float4*>(W4cT);

    for (int n0 = blockIdx.x * 16; n0 < NN; n0 += gridDim.x * 16) {
        int n = n0 + g;
        __syncthreads();
        float4 mrow = reinterpret_cast<const float4*>(mu)[n * 16 + q];
        *reinterpret_cast<float4*>(&mus[g * 68 + 4 * q]) = mrow;
        __syncthreads();

        float4 acc = make_float4(0.f, 0.f, 0.f, 0.f);
        #pragma unroll
        for (int k = 0; k < D; k++) {
            float m = mus[g * 68 + k];
            float4 w = W3T4[k * 16 + q];
            acc.x = fmaf(m, w.x, acc.x); acc.y = fmaf(m, w.y, acc.y);
            acc.z = fmaf(m, w.z, acc.z); acc.w = fmaf(m, w.w, acc.w);
        }
        float4 h = make_float4(fmaxf(acc.x, 0.f), fmaxf(acc.y, 0.f),
                               fmaxf(acc.z, 0.f), fmaxf(acc.w, 0.f));
        *reinterpret_cast<float4*>(&hs[g * 68 + 4 * q]) = h;
        __syncthreads();

        float4 acc2 = make_float4(0.f, 0.f, 0.f, 0.f);
        #pragma unroll
        for (int j = 0; j < D; j++) {
            float hv = hs[g * 68 + j];
            float4 w = W4cT4[j * 16 + q];
            acc2.x = fmaf(hv, w.x, acc2.x); acc2.y = fmaf(hv, w.y, acc2.y);
            acc2.z = fmaf(hv, w.z, acc2.z); acc2.w = fmaf(hv, w.w, acc2.w);
        }
        g_hmu4[n * 16 + q] = h;
        g_hmw4[n * 16 + q] = acc2;
    }
}

// ---- edge scatter: per edge, gather hmw[dst] (64 f32) -> red.v4 into S[src];
//      plus ONE packed red.v4 of the 4 per-node scalar sums. ----
__global__ __launch_bounds__(256) void edge_kernel(const int* __restrict__ ei,
                                                   const float* __restrict__ ew,
                                                   const float* __restrict__ x) {
    int warp = blockIdx.x * 8 + (threadIdx.x >> 5);
    int lane = threadIdx.x & 31;
    int sub  = lane >> 4;            // which of the warp's 2 edges
    int q    = lane & 15;            // quarter index: floats 4q..4q+3
    int e = warp * 2 + sub;          // grid sized exactly: e < EE

    int src = ei[e];
    int dst = ei[EE + e];

    if (q == 0) {
        float xv = x[dst];
        float w  = ew[e];
        float* ps = reinterpret_cast<float*>(&g_scal[src]);
        asm volatile("red.global.add.v4.f32 [%0], {%1,%2,%3,%4};"
                     :: "l"(ps), "f"(fmaxf(xv, 0.f)), "f"(fmaxf(-xv, 0.f)),
                        "f"(fmaxf(w, 0.f)), "f"(fmaxf(-w, 0.f))
                     : "memory");
    }

    float4 v = g_hmw4[dst * 16 + q];
    float* p = reinterpret_cast<float*>(&g_S4[src * 16 + q]);
    asm volatile("red.global.add.v4.f32 [%0], {%1,%2,%3,%4};"
                 :: "l"(p), "f"(v.x), "f"(v.y), "f"(v.z), "f"(v.w)
                 : "memory");
}

// ---- epilogue: out = relu(h_x + h_mu + relu(z)); restores accumulators to zero ----
__global__ __launch_bounds__(256) void final_kernel(const float* __restrict__ x,
                                                    const float* __restrict__ W1,
                                                    float* __restrict__ out) {
    int i = blockIdx.x * blockDim.x + threadIdx.x;   // grid covers NN*64 exactly
    int n = i >> 6, o = i & 63;
    float* S   = reinterpret_cast<float*>(g_S4);
    const float* hmu = reinterpret_cast<const float*>(g_hmu4);

    float4 sc = g_scal[n];                 // read by all 64 threads of node n
    float  s  = S[i];
    __syncthreads();                       // all reads done before re-zeroing
    S[i] = 0.0f;                           // restore invariant for next replay
    if (o == 0) g_scal[n] = make_float4(0.f, 0.f, 0.f, 0.f);

    float z = fmaf(sc.x, g_a1[o], fmaf(sc.y, g_a2[o],
              fmaf(sc.z, g_b1[o], fmaf(sc.w, g_b2[o], s))));
    float hx = fmaxf(x[n] * W1[o], 0.f);
    out[i] = fmaxf(hx + hmu[i] + fmaxf(z, 0.f), 0.f);
}

extern "C" void kernel_launch(void* const* d_in, const int* in_sizes, int n_in,
                              void* d_out, int out_size) {
    const float* mu = (const float*)d_in[0];
    const float* x  = (const float*)d_in[1];
    const int*   ei = (const int*)d_in[2];
    const float* ew = (const float*)d_in[3];
    const float* W1 = (const float*)d_in[4];
    const float* W2 = (const float*)d_in[5];
    const float* W3 = (const float*)d_in[6];
    const float* W4 = (const float*)d_in[7];
    float* out = (float*)d_out;

    vec_kernel<<<1, 64>>>(W1, W2, W4);
    gemm_kernel<<<888, 256>>>(mu, W3, W4);
    edge_kernel<<<EE / 16, 256>>>(ei, ew, x);   // 100000 blocks, 16 edges each
    final_kernel<<<(NN * D) / 256, 256>>>(x, W1, out);
}